// round 4
// baseline (speedup 1.0000x reference)
#include <cuda_runtime.h>
#include <cuda_bf16.h>
#include <stdint.h>

// Fused gather-concat:
//   out[r, 0:8]  = proc_pos[process_ids[r], :]   (16x8 f32 table -> smem)
//   out[r, 8:11] = locs_sp[location_ids[r], :]   (500000x3 f32, gathered; fits in L2)
//
// Index dtype (int32 vs int64) is detected on-device: an int64 id buffer with
// values < 500000 looks like (v,0,v,0,...) when viewed as int32 words.
//
// Block of 256 threads stages 256 rows (256*11 f32 = 11264 B) in shared memory,
// then flushes with fully-coalesced float4 stores (stride-11 staging is
// bank-conflict-free; 11264 B is 16B-divisible so every block's flush is aligned).

#define ROWS_PER_BLOCK 256
#define PROC_DIM 8
#define SP_DIM 3
#define OUT_DIM 11

__device__ int g_ids_are_i64;

__global__ void detect_id_dtype_kernel(const int* __restrict__ loc_ids_w, int naug)
{
    // Inspect 64 id slots. If the buffer is int64 (little-endian, values <
    // 500000), every odd 32-bit word is 0. For random int32 ids the chance of
    // that is ~(2e-6)^64 ~= 0.
    int n_check = naug < 64 ? naug : 64;
    int i64_like = 1;
    for (int i = 0; i < n_check; i++) {
        if (loc_ids_w[2 * i + 1] != 0) { i64_like = 0; break; }
    }
    g_ids_are_i64 = i64_like;
}

__global__ __launch_bounds__(ROWS_PER_BLOCK)
void gather_concat_kernel(
    const float* __restrict__ proc_pos,   // [num_procs, 8]
    const float* __restrict__ locs_sp,    // [num_locs, 3]
    const void*  __restrict__ process_ids,
    const void*  __restrict__ location_ids,
    float* __restrict__ out,              // [naug, 11]
    int naug,
    int num_procs,
    int num_locs)
{
    __shared__ float s_proc[512];                        // proc table
    __shared__ float s_stage[ROWS_PER_BLOCK * OUT_DIM];  // 11264 B

    const int tid = threadIdx.x;

    const int proc_elems = num_procs * PROC_DIM;
    for (int i = tid; i < proc_elems; i += ROWS_PER_BLOCK)
        s_proc[i] = proc_pos[i];
    __syncthreads();

    const long long base = (long long)blockIdx.x * ROWS_PER_BLOCK;
    const int row = (int)base + tid;          // naug = 8e6 fits int32
    const int ids64 = g_ids_are_i64;          // uniform across grid

    if (row < naug) {
        int pid, lid;
        if (ids64) {
            pid = (int)((const long long*)process_ids)[row];
            lid = (int)((const long long*)location_ids)[row];
        } else {
            pid = ((const int*)process_ids)[row];
            lid = ((const int*)location_ids)[row];
        }
        // Clamp: a wrong dtype guess then yields wrong values, not a fault.
        pid = min(max(pid, 0), num_procs - 1);
        lid = min(max(lid, 0), num_locs - 1);

        float* dst = &s_stage[tid * OUT_DIM];

        const float* p = &s_proc[pid * PROC_DIM];
        #pragma unroll
        for (int c = 0; c < PROC_DIM; c++)
            dst[c] = p[c];

        const float* l = &locs_sp[(size_t)lid * SP_DIM];
        #pragma unroll
        for (int c = 0; c < SP_DIM; c++)
            dst[PROC_DIM + c] = __ldg(&l[c]);
    }
    __syncthreads();

    if (base + ROWS_PER_BLOCK <= (long long)naug) {
        // Full block: 704 float4 coalesced stores.
        const float4* s4 = (const float4*)s_stage;
        float4* o4 = (float4*)(out + (size_t)base * OUT_DIM);
        #pragma unroll
        for (int i = tid; i < (ROWS_PER_BLOCK * OUT_DIM) / 4; i += ROWS_PER_BLOCK)
            o4[i] = s4[i];
    } else {
        // Tail block (not hit for naug = 8M): scalar flush.
        const int nrows = naug - (int)base;
        const int total = nrows * OUT_DIM;
        float* o = out + (size_t)base * OUT_DIM;
        for (int i = tid; i < total; i += ROWS_PER_BLOCK)
            o[i] = s_stage[i];
    }
}

extern "C" void kernel_launch(void* const* d_in, const int* in_sizes, int n_in,
                              void* d_out, int out_size) {
    const float* proc_pos     = (const float*)d_in[0];
    const float* locs_sp      = (const float*)d_in[1];
    const void*  process_ids  = d_in[2];
    const void*  location_ids = d_in[3];
    float* out = (float*)d_out;

    const int naug      = in_sizes[2];              // 8,000,000
    const int num_procs = in_sizes[0] / PROC_DIM;   // 16
    const int num_locs  = in_sizes[1] / SP_DIM;     // 500,000

    detect_id_dtype_kernel<<<1, 1>>>((const int*)location_ids, naug);

    const int grid = (naug + ROWS_PER_BLOCK - 1) / ROWS_PER_BLOCK;
    gather_concat_kernel<<<grid, ROWS_PER_BLOCK>>>(
        proc_pos, locs_sp, process_ids, location_ids, out,
        naug, num_procs, num_locs);
}

// round 5
// speedup vs baseline: 1.0846x; 1.0846x over previous
#include <cuda_runtime.h>
#include <cuda_bf16.h>
#include <stdint.h>

// Fused gather-concat:
//   out[r, 0:8]  = proc_pos[process_ids[r], :]   (16x8 f32 table -> smem, TRANSPOSED)
//   out[r, 8:11] = locs_sp[location_ids[r], :]   (500000x3 f32, gathered; L2-resident)
//
// R4 ncu: L1=81% (bound), DRAM=38%. Cause: s_proc[pid*8+c] puts all 16 pids on
// only 4 banks per column -> up to 8-way LDS conflicts on 8 loads/row.
// Fix: transposed table s_procT[c*16+pid] -> for fixed c, the 16 pids hit 16
// distinct banks; duplicate pids broadcast. Conflict-free.
//
// Staging (stride-11 rows, odd => conflict-free STS) + float4 flush keeps
// stores fully coalesced (256 rows * 44 B = 11264 B, 16B-divisible).

#define ROWS_PER_BLOCK 256
#define PROC_DIM 8
#define SP_DIM 3
#define OUT_DIM 11

__device__ int g_ids_are_i64;

__global__ void detect_id_dtype_kernel(const int* __restrict__ loc_ids_w, int naug)
{
    // int64 little-endian ids with values < 500000 look like (v,0,v,0,...):
    // every odd 32-bit word is zero. Random int32 ids: P(all 64 zero) ~ 0.
    int n_check = naug < 64 ? naug : 64;
    int i64_like = 1;
    for (int i = 0; i < n_check; i++) {
        if (loc_ids_w[2 * i + 1] != 0) { i64_like = 0; break; }
    }
    g_ids_are_i64 = i64_like;
}

__global__ __launch_bounds__(ROWS_PER_BLOCK)
void gather_concat_kernel(
    const float* __restrict__ proc_pos,   // [num_procs, 8]
    const float* __restrict__ locs_sp,    // [num_locs, 3]
    const void*  __restrict__ process_ids,
    const void*  __restrict__ location_ids,
    float* __restrict__ out,              // [naug, 11]
    int naug,
    int num_procs,
    int num_locs)
{
    __shared__ float s_procT[PROC_DIM * 64];              // transposed: [c][pid], pid stride 1
    __shared__ float s_stage[ROWS_PER_BLOCK * OUT_DIM];   // 11264 B

    const int tid = threadIdx.x;

    // Load proc table transposed: s_procT[c*num_procs + pid] = proc_pos[pid*8 + c].
    const int proc_elems = num_procs * PROC_DIM;
    for (int i = tid; i < proc_elems; i += ROWS_PER_BLOCK) {
        const int pid = i / PROC_DIM;
        const int c   = i % PROC_DIM;
        s_procT[c * num_procs + pid] = proc_pos[i];
    }
    __syncthreads();

    const long long base = (long long)blockIdx.x * ROWS_PER_BLOCK;
    const int row = (int)base + tid;          // naug = 8e6 fits int32
    const int ids64 = g_ids_are_i64;          // uniform across grid

    if (row < naug) {
        int pid, lid;
        if (ids64) {
            pid = (int)((const long long*)process_ids)[row];
            lid = (int)((const long long*)location_ids)[row];
        } else {
            pid = ((const int*)process_ids)[row];
            lid = ((const int*)location_ids)[row];
        }
        // Clamp: wrong dtype guess yields wrong values, not a fault.
        pid = min(max(pid, 0), num_procs - 1);
        lid = min(max(lid, 0), num_locs - 1);

        float* dst = &s_stage[tid * OUT_DIM];

        // Conflict-free gather from transposed table.
        #pragma unroll
        for (int c = 0; c < PROC_DIM; c++)
            dst[c] = s_procT[c * num_procs + pid];

        // 3 floats gathered from locs_sp (6 MB table, L2-resident).
        const float* l = &locs_sp[(size_t)lid * SP_DIM];
        #pragma unroll
        for (int c = 0; c < SP_DIM; c++)
            dst[PROC_DIM + c] = __ldg(&l[c]);
    }
    __syncthreads();

    if (base + ROWS_PER_BLOCK <= (long long)naug) {
        // Full block: 704 float4 coalesced stores.
        const float4* s4 = (const float4*)s_stage;
        float4* o4 = (float4*)(out + (size_t)base * OUT_DIM);
        #pragma unroll
        for (int i = tid; i < (ROWS_PER_BLOCK * OUT_DIM) / 4; i += ROWS_PER_BLOCK)
            o4[i] = s4[i];
    } else {
        // Tail block (not hit for naug = 8M): scalar flush.
        const int nrows = naug - (int)base;
        const int total = nrows * OUT_DIM;
        float* o = out + (size_t)base * OUT_DIM;
        for (int i = tid; i < total; i += ROWS_PER_BLOCK)
            o[i] = s_stage[i];
    }
}

extern "C" void kernel_launch(void* const* d_in, const int* in_sizes, int n_in,
                              void* d_out, int out_size) {
    const float* proc_pos     = (const float*)d_in[0];
    const float* locs_sp      = (const float*)d_in[1];
    const void*  process_ids  = d_in[2];
    const void*  location_ids = d_in[3];
    float* out = (float*)d_out;

    const int naug      = in_sizes[2];              // 8,000,000
    const int num_procs = in_sizes[0] / PROC_DIM;   // 16
    const int num_locs  = in_sizes[1] / SP_DIM;     // 500,000

    detect_id_dtype_kernel<<<1, 1>>>((const int*)location_ids, naug);

    const int grid = (naug + ROWS_PER_BLOCK - 1) / ROWS_PER_BLOCK;
    gather_concat_kernel<<<grid, ROWS_PER_BLOCK>>>(
        proc_pos, locs_sp, process_ids, location_ids, out,
        naug, num_procs, num_locs);
}

// round 6
// speedup vs baseline: 1.1934x; 1.1003x over previous
#include <cuda_runtime.h>
#include <cuda_bf16.h>
#include <stdint.h>

// Fused gather-concat:
//   out[r, 0:8]  = proc_pos[process_ids[r], :]   (16x8 f32 -> smem, transposed)
//   out[r, 8:11] = locs_sp[location_ids[r], :]   (500000x3 f32)
//
// R5 ncu: L1=70.9% still binding. Remaining hot spot: the locs_sp gather is 3
// scalar LDGs per row at random addresses -> 3x L1 wavefront cost for one 12B
// span. Fix: pre-pad locs_sp into a float4 table (__device__ global scratch),
// gather with ONE 16B-aligned LDG.128 per row.
//
// Staging (stride-11 rows, conflict-free STS) + float4 flush keeps stores
// fully coalesced (256 rows * 44 B = 11264 B, 16B-divisible per block).

#define ROWS_PER_BLOCK 256
#define PROC_DIM 8
#define SP_DIM 3
#define OUT_DIM 11
#define MAX_LOCS 500000

__device__ int g_ids_are_i64;
__device__ float4 g_locs_pad[MAX_LOCS];   // 8 MB static scratch

__global__ void detect_id_dtype_kernel(const int* __restrict__ loc_ids_w, int naug)
{
    // int64 little-endian ids with values < 500000 look like (v,0,v,0,...):
    // every odd 32-bit word is zero. Random int32 ids: P(all 64 zero) ~ 0.
    int n_check = naug < 64 ? naug : 64;
    int i64_like = 1;
    for (int i = 0; i < n_check; i++) {
        if (loc_ids_w[2 * i + 1] != 0) { i64_like = 0; break; }
    }
    g_ids_are_i64 = i64_like;
}

// Pad [num_locs, 3] -> float4 table (w unused). Coalesced read + write.
__global__ __launch_bounds__(256)
void pad_locs_kernel(const float* __restrict__ locs_sp, int num_locs)
{
    int i = blockIdx.x * blockDim.x + threadIdx.x;
    if (i < num_locs) {
        const float* s = locs_sp + (size_t)i * SP_DIM;
        float4 v;
        v.x = s[0]; v.y = s[1]; v.z = s[2]; v.w = 0.0f;
        g_locs_pad[i] = v;
    }
}

__global__ __launch_bounds__(ROWS_PER_BLOCK)
void gather_concat_kernel(
    const float* __restrict__ proc_pos,   // [num_procs, 8]
    const float* __restrict__ locs_sp,    // [num_locs, 3] (fallback path only)
    const void*  __restrict__ process_ids,
    const void*  __restrict__ location_ids,
    float* __restrict__ out,              // [naug, 11]
    int naug,
    int num_procs,
    int num_locs,
    int use_padded)
{
    __shared__ float s_procT[PROC_DIM * 64];              // transposed [c][pid]
    __shared__ float s_stage[ROWS_PER_BLOCK * OUT_DIM];   // 11264 B

    const int tid = threadIdx.x;

    const int proc_elems = num_procs * PROC_DIM;
    for (int i = tid; i < proc_elems; i += ROWS_PER_BLOCK) {
        const int pid = i / PROC_DIM;
        const int c   = i % PROC_DIM;
        s_procT[c * num_procs + pid] = proc_pos[i];
    }
    __syncthreads();

    const long long base = (long long)blockIdx.x * ROWS_PER_BLOCK;
    const int row = (int)base + tid;          // naug = 8e6 fits int32
    const int ids64 = g_ids_are_i64;          // uniform across grid

    if (row < naug) {
        int pid, lid;
        if (ids64) {
            pid = (int)((const long long*)process_ids)[row];
            lid = (int)((const long long*)location_ids)[row];
        } else {
            pid = ((const int*)process_ids)[row];
            lid = ((const int*)location_ids)[row];
        }
        pid = min(max(pid, 0), num_procs - 1);
        lid = min(max(lid, 0), num_locs - 1);

        float* dst = &s_stage[tid * OUT_DIM];

        // Conflict-free gather from transposed smem table.
        #pragma unroll
        for (int c = 0; c < PROC_DIM; c++)
            dst[c] = s_procT[c * num_procs + pid];

        // Location gather: single aligned 16B load from padded table.
        if (use_padded) {
            float4 v = __ldg(&g_locs_pad[lid]);
            dst[PROC_DIM + 0] = v.x;
            dst[PROC_DIM + 1] = v.y;
            dst[PROC_DIM + 2] = v.z;
        } else {
            const float* l = &locs_sp[(size_t)lid * SP_DIM];
            #pragma unroll
            for (int c = 0; c < SP_DIM; c++)
                dst[PROC_DIM + c] = __ldg(&l[c]);
        }
    }
    __syncthreads();

    if (base + ROWS_PER_BLOCK <= (long long)naug) {
        // Full block: 704 float4 coalesced stores.
        const float4* s4 = (const float4*)s_stage;
        float4* o4 = (float4*)(out + (size_t)base * OUT_DIM);
        #pragma unroll
        for (int i = tid; i < (ROWS_PER_BLOCK * OUT_DIM) / 4; i += ROWS_PER_BLOCK)
            o4[i] = s4[i];
    } else {
        // Tail block (not hit for naug = 8M): scalar flush.
        const int nrows = naug - (int)base;
        const int total = nrows * OUT_DIM;
        float* o = out + (size_t)base * OUT_DIM;
        for (int i = tid; i < total; i += ROWS_PER_BLOCK)
            o[i] = s_stage[i];
    }
}

extern "C" void kernel_launch(void* const* d_in, const int* in_sizes, int n_in,
                              void* d_out, int out_size) {
    const float* proc_pos     = (const float*)d_in[0];
    const float* locs_sp      = (const float*)d_in[1];
    const void*  process_ids  = d_in[2];
    const void*  location_ids = d_in[3];
    float* out = (float*)d_out;

    const int naug      = in_sizes[2];              // 8,000,000
    const int num_procs = in_sizes[0] / PROC_DIM;   // 16
    const int num_locs  = in_sizes[1] / SP_DIM;     // 500,000
    const int use_padded = (num_locs <= MAX_LOCS) ? 1 : 0;

    detect_id_dtype_kernel<<<1, 1>>>((const int*)location_ids, naug);

    if (use_padded) {
        const int pg = (num_locs + 255) / 256;
        pad_locs_kernel<<<pg, 256>>>(locs_sp, num_locs);
    }

    const int grid = (naug + ROWS_PER_BLOCK - 1) / ROWS_PER_BLOCK;
    gather_concat_kernel<<<grid, ROWS_PER_BLOCK>>>(
        proc_pos, locs_sp, process_ids, location_ids, out,
        naug, num_procs, num_locs, use_padded);
}

// round 7
// speedup vs baseline: 1.2342x; 1.0342x over previous
#include <cuda_runtime.h>
#include <cuda_bf16.h>
#include <stdint.h>

// Fused gather-concat:
//   out[r, 0:8]  = proc_pos[process_ids[r], :]   (16x8 f32 -> smem, transposed)
//   out[r, 8:11] = locs_sp[location_ids[r], :]   (500000x3 f32 -> padded float4 table)
//
// R6: detect kernel was 4.4us of serial DRAM loads -> folded into the pad
// kernel (parallel check, one fewer launch). Streaming hints: ids read-once
// (__ldcs), output write-once (__stcs) so the 8MB padded gather table stays
// L2-resident instead of being evicted by 480MB of streaming traffic.

#define ROWS_PER_BLOCK 256
#define PROC_DIM 8
#define SP_DIM 3
#define OUT_DIM 11
#define MAX_LOCS 500000

__device__ int g_ids_are_i64;
__device__ float4 g_locs_pad[MAX_LOCS];   // 8 MB static scratch

// Pad [num_locs,3] -> float4 table; block 0 also detects the id dtype.
__global__ __launch_bounds__(256)
void setup_kernel(const float* __restrict__ locs_sp, int num_locs,
                  const int* __restrict__ loc_ids_w, int naug)
{
    int i = blockIdx.x * blockDim.x + threadIdx.x;
    if (i < num_locs) {
        const float* s = locs_sp + (size_t)i * SP_DIM;
        float4 v;
        v.x = s[0]; v.y = s[1]; v.z = s[2]; v.w = 0.0f;
        g_locs_pad[i] = v;
    }

    // Dtype detection (block 0): int64 little-endian ids with values < 5e5
    // look like (v,0,v,0,...) -> every odd 32-bit word is zero. For random
    // int32 ids, P(64 odd words all zero) ~ (2e-6)^32 ~ 0.
    if (blockIdx.x == 0) {
        __shared__ int s_not64;
        if (threadIdx.x == 0) s_not64 = 0;
        __syncthreads();
        int n_check = naug < 64 ? naug : 64;
        if (threadIdx.x < n_check) {
            if (loc_ids_w[2 * threadIdx.x + 1] != 0) atomicOr(&s_not64, 1);
        }
        __syncthreads();
        if (threadIdx.x == 0) g_ids_are_i64 = s_not64 ? 0 : 1;
    }
}

__global__ __launch_bounds__(ROWS_PER_BLOCK)
void gather_concat_kernel(
    const float* __restrict__ proc_pos,   // [num_procs, 8]
    const float* __restrict__ locs_sp,    // [num_locs, 3] (fallback path only)
    const void*  __restrict__ process_ids,
    const void*  __restrict__ location_ids,
    float* __restrict__ out,              // [naug, 11]
    int naug,
    int num_procs,
    int num_locs,
    int use_padded)
{
    __shared__ float s_procT[PROC_DIM * 64];              // transposed [c][pid]
    __shared__ float s_stage[ROWS_PER_BLOCK * OUT_DIM];   // 11264 B

    const int tid = threadIdx.x;

    const int proc_elems = num_procs * PROC_DIM;
    for (int i = tid; i < proc_elems; i += ROWS_PER_BLOCK) {
        const int pid = i / PROC_DIM;
        const int c   = i % PROC_DIM;
        s_procT[c * num_procs + pid] = proc_pos[i];
    }
    __syncthreads();

    const long long base = (long long)blockIdx.x * ROWS_PER_BLOCK;
    const int row = (int)base + tid;          // naug = 8e6 fits int32
    const int ids64 = g_ids_are_i64;          // uniform across grid

    if (row < naug) {
        int pid, lid;
        if (ids64) {
            pid = (int)__ldcs(&((const long long*)process_ids)[row]);
            lid = (int)__ldcs(&((const long long*)location_ids)[row]);
        } else {
            pid = __ldcs(&((const int*)process_ids)[row]);
            lid = __ldcs(&((const int*)location_ids)[row]);
        }
        pid = min(max(pid, 0), num_procs - 1);
        lid = min(max(lid, 0), num_locs - 1);

        float* dst = &s_stage[tid * OUT_DIM];

        // Conflict-free gather from transposed smem table.
        #pragma unroll
        for (int c = 0; c < PROC_DIM; c++)
            dst[c] = s_procT[c * num_procs + pid];

        // Location gather: single aligned 16B load from padded table (L2-hot).
        if (use_padded) {
            float4 v = __ldg(&g_locs_pad[lid]);
            dst[PROC_DIM + 0] = v.x;
            dst[PROC_DIM + 1] = v.y;
            dst[PROC_DIM + 2] = v.z;
        } else {
            const float* l = &locs_sp[(size_t)lid * SP_DIM];
            #pragma unroll
            for (int c = 0; c < SP_DIM; c++)
                dst[PROC_DIM + c] = __ldg(&l[c]);
        }
    }
    __syncthreads();

    if (base + ROWS_PER_BLOCK <= (long long)naug) {
        // Full block: 704 float4 coalesced streaming stores.
        const float4* s4 = (const float4*)s_stage;
        float4* o4 = (float4*)(out + (size_t)base * OUT_DIM);
        #pragma unroll
        for (int i = tid; i < (ROWS_PER_BLOCK * OUT_DIM) / 4; i += ROWS_PER_BLOCK)
            __stcs(&o4[i], s4[i]);
    } else {
        // Tail block (not hit for naug = 8M): scalar flush.
        const int nrows = naug - (int)base;
        const int total = nrows * OUT_DIM;
        float* o = out + (size_t)base * OUT_DIM;
        for (int i = tid; i < total; i += ROWS_PER_BLOCK)
            o[i] = s_stage[i];
    }
}

extern "C" void kernel_launch(void* const* d_in, const int* in_sizes, int n_in,
                              void* d_out, int out_size) {
    const float* proc_pos     = (const float*)d_in[0];
    const float* locs_sp      = (const float*)d_in[1];
    const void*  process_ids  = d_in[2];
    const void*  location_ids = d_in[3];
    float* out = (float*)d_out;

    const int naug      = in_sizes[2];              // 8,000,000
    const int num_procs = in_sizes[0] / PROC_DIM;   // 16
    const int num_locs  = in_sizes[1] / SP_DIM;     // 500,000
    const int use_padded = (num_locs <= MAX_LOCS) ? 1 : 0;

    {
        // Always launch: detection must run even if padding is skipped.
        const int work = use_padded ? num_locs : 256;
        const int pg = (work + 255) / 256;
        setup_kernel<<<pg, 256>>>(locs_sp, use_padded ? num_locs : 0,
                                  (const int*)location_ids, naug);
    }

    const int grid = (naug + ROWS_PER_BLOCK - 1) / ROWS_PER_BLOCK;
    gather_concat_kernel<<<grid, ROWS_PER_BLOCK>>>(
        proc_pos, locs_sp, process_ids, location_ids, out,
        naug, num_procs, num_locs, use_padded);
}

// round 8
// speedup vs baseline: 1.2427x; 1.0068x over previous
#include <cuda_runtime.h>
#include <cuda_bf16.h>
#include <stdint.h>

// Fused gather-concat:
//   out[r, 0:8]  = proc_pos[process_ids[r], :]   (16x8 f32 -> smem, transposed)
//   out[r, 8:11] = locs_sp[location_ids[r], :]   (500000x3 f32 -> padded float4 table)
//
// R7 ncu: L1=71.5% still binding. The random float4 gather is ~32 L1
// wavefronts/warp with ~0 L1 hit rate (8MB table vs 228KB L1) -> bypass L1
// entirely with __ldcg (L2-cached). ids are read-once (__ldcs), output is
// write-once (__stcs). Staging: stride-11 smem rows (conflict-free STS) +
// float4 flush = fully coalesced 352MB store stream.

#define ROWS_PER_BLOCK 256
#define PROC_DIM 8
#define SP_DIM 3
#define OUT_DIM 11
#define MAX_LOCS 500000

__device__ int g_ids_are_i64;
__device__ float4 g_locs_pad[MAX_LOCS];   // 8 MB static scratch

// Pad [num_locs,3] -> float4 table; block 0 also detects the id dtype.
__global__ __launch_bounds__(256)
void setup_kernel(const float* __restrict__ locs_sp, int num_locs,
                  const int* __restrict__ loc_ids_w, int naug)
{
    int i = blockIdx.x * blockDim.x + threadIdx.x;
    if (i < num_locs) {
        const float* s = locs_sp + (size_t)i * SP_DIM;
        float4 v;
        v.x = s[0]; v.y = s[1]; v.z = s[2]; v.w = 0.0f;
        g_locs_pad[i] = v;
    }

    // Dtype detection (block 0): int64 little-endian ids with values < 5e5
    // look like (v,0,v,0,...) -> every odd 32-bit word is zero. For random
    // int32 ids, P(64 odd words all zero) ~ 0.
    if (blockIdx.x == 0) {
        __shared__ int s_not64;
        if (threadIdx.x == 0) s_not64 = 0;
        __syncthreads();
        int n_check = naug < 64 ? naug : 64;
        if (threadIdx.x < n_check) {
            if (loc_ids_w[2 * threadIdx.x + 1] != 0) atomicOr(&s_not64, 1);
        }
        __syncthreads();
        if (threadIdx.x == 0) g_ids_are_i64 = s_not64 ? 0 : 1;
    }
}

__global__ __launch_bounds__(ROWS_PER_BLOCK)
void gather_concat_kernel(
    const float* __restrict__ proc_pos,   // [num_procs, 8]
    const float* __restrict__ locs_sp,    // [num_locs, 3] (fallback path only)
    const void*  __restrict__ process_ids,
    const void*  __restrict__ location_ids,
    float* __restrict__ out,              // [naug, 11]
    int naug,
    int num_procs,
    int num_locs,
    int use_padded)
{
    __shared__ float s_procT[PROC_DIM * 64];              // transposed [c][pid]
    __shared__ float s_stage[ROWS_PER_BLOCK * OUT_DIM];   // 11264 B

    const int tid = threadIdx.x;

    const int proc_elems = num_procs * PROC_DIM;
    for (int i = tid; i < proc_elems; i += ROWS_PER_BLOCK) {
        const int pid = i / PROC_DIM;
        const int c   = i % PROC_DIM;
        s_procT[c * num_procs + pid] = proc_pos[i];
    }
    __syncthreads();

    const long long base = (long long)blockIdx.x * ROWS_PER_BLOCK;
    const int row = (int)base + tid;          // naug = 8e6 fits int32
    const int ids64 = g_ids_are_i64;          // uniform across grid

    if (row < naug) {
        int pid, lid;
        if (ids64) {
            pid = (int)__ldcs(&((const long long*)process_ids)[row]);
            lid = (int)__ldcs(&((const long long*)location_ids)[row]);
        } else {
            pid = __ldcs(&((const int*)process_ids)[row]);
            lid = __ldcs(&((const int*)location_ids)[row]);
        }
        pid = min(max(pid, 0), num_procs - 1);
        lid = min(max(lid, 0), num_locs - 1);

        float* dst = &s_stage[tid * OUT_DIM];

        // Conflict-free gather from transposed smem table.
        #pragma unroll
        for (int c = 0; c < PROC_DIM; c++)
            dst[c] = s_procT[c * num_procs + pid];

        // Location gather: single 16B load, L1-BYPASSED (no reuse in L1;
        // table is L2-resident).
        if (use_padded) {
            float4 v = __ldcg(&g_locs_pad[lid]);
            dst[PROC_DIM + 0] = v.x;
            dst[PROC_DIM + 1] = v.y;
            dst[PROC_DIM + 2] = v.z;
        } else {
            const float* l = &locs_sp[(size_t)lid * SP_DIM];
            #pragma unroll
            for (int c = 0; c < SP_DIM; c++)
                dst[PROC_DIM + c] = __ldcg(&l[c]);
        }
    }
    __syncthreads();

    if (base + ROWS_PER_BLOCK <= (long long)naug) {
        // Full block: 704 float4 coalesced streaming stores.
        const float4* s4 = (const float4*)s_stage;
        float4* o4 = (float4*)(out + (size_t)base * OUT_DIM);
        #pragma unroll
        for (int i = tid; i < (ROWS_PER_BLOCK * OUT_DIM) / 4; i += ROWS_PER_BLOCK)
            __stcs(&o4[i], s4[i]);
    } else {
        // Tail block (not hit for naug = 8M): scalar flush.
        const int nrows = naug - (int)base;
        const int total = nrows * OUT_DIM;
        float* o = out + (size_t)base * OUT_DIM;
        for (int i = tid; i < total; i += ROWS_PER_BLOCK)
            o[i] = s_stage[i];
    }
}

extern "C" void kernel_launch(void* const* d_in, const int* in_sizes, int n_in,
                              void* d_out, int out_size) {
    const float* proc_pos     = (const float*)d_in[0];
    const float* locs_sp      = (const float*)d_in[1];
    const void*  process_ids  = d_in[2];
    const void*  location_ids = d_in[3];
    float* out = (float*)d_out;

    const int naug      = in_sizes[2];              // 8,000,000
    const int num_procs = in_sizes[0] / PROC_DIM;   // 16
    const int num_locs  = in_sizes[1] / SP_DIM;     // 500,000
    const int use_padded = (num_locs <= MAX_LOCS) ? 1 : 0;

    {
        const int work = use_padded ? num_locs : 256;
        const int pg = (work + 255) / 256;
        setup_kernel<<<pg, 256>>>(locs_sp, use_padded ? num_locs : 0,
                                  (const int*)location_ids, naug);
    }

    const int grid = (naug + ROWS_PER_BLOCK - 1) / ROWS_PER_BLOCK;
    gather_concat_kernel<<<grid, ROWS_PER_BLOCK>>>(
        proc_pos, locs_sp, process_ids, location_ids, out,
        naug, num_procs, num_locs, use_padded);
}